// round 17
// baseline (speedup 1.0000x reference)
#include <cuda_runtime.h>
#include <cuda_fp16.h>
#include <cstdint>
#include <math.h>

#define B_    64
#define T_    2048
#define ENC   512
#define QD    256
#define AD    128
#define CH    32
#define KS    31
#define PADK  15

#define MT     64       // t-rows per CTA (3 CTAs/SM)
#define KCH    64       // k per chunk (64 fp16 = 128B rows, SW128)
#define NCHUNK 9        // 8 enc chunks + 1 location chunk

// ---- dynamic smem layout (relative to 1024-aligned base) ----
#define OFF_A    0              // two stages of 8 KB (A single-term fp16)
#define ASTAGE   8192
#define OFF_B    16384          // THREE stages of 16 KB (B single fp16)
#define BSTAGE   16384
#define OFF_QB   65536          // 128 floats
#define OFF_VV   (OFF_QB + 512)
#define OFF_PREV (OFF_VV + 512)   // 94 floats (pad 384)
#define OFF_PART (OFF_PREV + 384) // 4*64 floats = 1024B
#define SMEM_REQ (OFF_PART + 1024 + 2048)   // + alignment slack (~69.5 KB)

// ---- device scratch ----
__device__ __align__(16) float g_energy[B_ * T_];
__device__ float         g_qb[B_ * AD];
__device__ __align__(16) __half g_BT[AD * ENC];      // Wk^T, K-major fp16
__device__ __align__(16) __half g_W2T[AD * KCH];     // W2^T fp16

// ============================ helpers ============================
__device__ __forceinline__ uint32_t smem_u32(const void* p) {
    uint32_t a;
    asm("{ .reg .u64 t; cvta.to.shared.u64 t, %1; cvt.u32.u64 %0, t; }"
        : "=r"(a) : "l"(p));
    return a;
}
__device__ __forceinline__ uint32_t sw128(uint32_t off) {
    return off ^ ((off >> 3) & 0x70);
}
// pack two floats -> f16x2 (f0 in low half)
__device__ __forceinline__ uint32_t pkh(float f0, float f1) {
    uint32_t r;
    asm("cvt.rn.f16x2.f32 %0, %1, %2;" : "=r"(r) : "f"(f1), "f"(f0));
    return r;
}
// convert 8 floats -> fp16 uint4 (single term)
__device__ __forceinline__ void cvt8h(const float* f, uint4& h) {
    h.x = pkh(f[0], f[1]); h.y = pkh(f[2], f[3]);
    h.z = pkh(f[4], f[5]); h.w = pkh(f[6], f[7]);
}
#define LDSM4(r0, r1, r2, r3, addr)                                            \
    asm volatile("ldmatrix.sync.aligned.m8n8.x4.shared.b16 {%0,%1,%2,%3}, [%4];" \
                 : "=r"(r0), "=r"(r1), "=r"(r2), "=r"(r3) : "r"(addr))
#define MMAH(c, a, b0, b1)                                                     \
    asm volatile("mma.sync.aligned.m16n8k16.row.col.f32.f16.f16.f32 "          \
                 "{%0,%1,%2,%3}, {%4,%5,%6,%7}, {%8,%9}, {%0,%1,%2,%3};"       \
                 : "+f"((c)[0]), "+f"((c)[1]), "+f"((c)[2]), "+f"((c)[3])      \
                 : "r"((a)[0]), "r"((a)[1]), "r"((a)[2]), "r"((a)[3]),         \
                   "r"(b0), "r"(b1))
#define CPASYNC16(dst, src)                                                    \
    asm volatile("cp.async.cg.shared.global [%0], [%1], 16;"                   \
                 :: "r"(dst), "l"(src))
#define CPCOMMIT() asm volatile("cp.async.commit_group;" ::: "memory")
#define CPWAIT1()  asm volatile("cp.async.wait_group 1;" ::: "memory")
#define CPWAIT0()  asm volatile("cp.async.wait_group 0;" ::: "memory")

// ---- stage A(chunk cc) fp32 into regs (volatile -> stays sunk) ----
__device__ __forceinline__ void stage_A_fn(float stA[2][8], int cc, int tid,
                                           const float* __restrict__ encb,
                                           const float* __restrict__ pv_s) {
    if (cc < 8) {
        const float* src = encb + cc * KCH;
        #pragma unroll
        for (int i = 0; i < 2; i++) {
            int idx = tid + i * 256;
            int row = idx >> 3, g = idx & 7;
            const float* p = src + (size_t)row * ENC + g * 8;
            asm volatile("ld.global.nc.v4.f32 {%0,%1,%2,%3}, [%4];"
                : "=f"(stA[i][0]), "=f"(stA[i][1]),
                  "=f"(stA[i][2]), "=f"(stA[i][3]) : "l"(p));
            asm volatile("ld.global.nc.v4.f32 {%0,%1,%2,%3}, [%4];"
                : "=f"(stA[i][4]), "=f"(stA[i][5]),
                  "=f"(stA[i][6]), "=f"(stA[i][7]) : "l"(p + 4));
        }
    } else {
        #pragma unroll
        for (int i = 0; i < 2; i++) {
            int idx = tid + i * 256;
            int row = idx >> 3, g = idx & 7;
            #pragma unroll
            for (int j = 0; j < 8; j++) {
                int k = g * 8 + j;
                stA[i][j] = (k < KS) ? pv_s[row + k] : 0.f;
            }
        }
    }
}
// ---- convert + STS staged A into buffer `buf` (0/1) ----
__device__ __forceinline__ void sts_A_fn(float stA[2][8], int buf, int tid,
                                         char* sm) {
    #pragma unroll
    for (int i = 0; i < 2; i++) {
        int idx = tid + i * 256;
        int row = idx >> 3, g = idx & 7;
        uint4 h; cvt8h(stA[i], h);
        uint32_t off = sw128((uint32_t)(row * 128 + g * 16));
        *(uint4*)(sm + OFF_A + buf * ASTAGE + off) = h;
    }
}
// ---- issue cp.async for B(chunk cc) into ring slot cc%3 ----
__device__ __forceinline__ void fill_B_fn(int cc, int tid, uint32_t base) {
    const __half* bsrc = (cc < 8) ? g_BT : g_W2T;
    const int stride = (cc < 8) ? ENC : KCH;
    const int coff   = (cc < 8) ? cc * KCH : 0;
    const uint32_t sb = base + OFF_B + (uint32_t)(cc % 3) * BSTAGE;
    #pragma unroll
    for (int i = 0; i < 4; i++) {
        int idx = tid + i * 256;
        int n = idx >> 3, g = idx & 7;
        uint32_t off = sw128((uint32_t)(n * 128 + g * 16));
        CPASYNC16(sb + off, bsrc + (size_t)n * stride + coff + g * 8);
    }
}

// ============================ merged prep kernel ============================
// grid 160 x 512:
//   [0,32):   BT transpose, 16 k-rows each (4 smem-load iters, 256 writers)
//   [32,96):  W2T (k = bx-32), first 128 threads
//   [96,160): qb (b = bx-96), 4-way q split + smem reduce
__global__ __launch_bounds__(512)
void prep_all_kernel(const float* __restrict__ Wk,
                     const float* __restrict__ conv_w,
                     const float* __restrict__ Wl,
                     const float* __restrict__ dec,
                     const float* __restrict__ Wq,
                     const float* __restrict__ conv_b) {
    int bx = blockIdx.x, tid = threadIdx.x;
    if (bx < 32) {
        __shared__ __half st[16 * 136];           // padded rows
        int k0 = bx * 16;
        #pragma unroll
        for (int p = 0; p < 4; p++) {
            int idx = tid + p * 512;              // 0..2047
            int r = idx >> 7, n = idx & 127;
            st[r * 136 + n] = __float2half_rn(Wk[(size_t)(k0 + r) * AD + n]);
        }
        __syncthreads();
        if (tid < 256) {
            int kg = tid >> 7, n = tid & 127;     // 2 groups of 8 k
            __half pack[8];
            #pragma unroll
            for (int j = 0; j < 8; j++)
                pack[j] = st[(kg * 8 + j) * 136 + n];
            *(uint4*)(g_BT + (size_t)n * ENC + k0 + kg * 8) =
                *(const uint4*)pack;
        }
    } else if (bx < 96) {
        if (tid < AD) {
            int k = bx - 32;
            float w = 0.f;
            if (k < KS) {
                #pragma unroll
                for (int c = 0; c < CH; c++)
                    w += conv_w[c * KS + k] * Wl[c * AD + tid];
            }
            g_W2T[tid * KCH + k] = __float2half_rn(w);
        }
    } else {
        __shared__ float qred[512];
        int b = bx - 96;
        int a = tid & 127, h = tid >> 7;          // 4-way q split
        float s = 0.f;
        #pragma unroll 8
        for (int q = h * 64; q < h * 64 + 64; q++)
            s += dec[b * QD + q] * Wq[q * AD + a];
        if (h == 0) {
            #pragma unroll
            for (int c = 0; c < CH; c++)
                s += conv_b[c] * Wl[c * AD + a];
        }
        qred[tid] = s;
        __syncthreads();
        if (tid < AD)
            g_qb[b * AD + tid] = (qred[tid] + qred[tid + 128])
                               + (qred[tid + 256] + qred[tid + 384]);
    }
}

// ============================ energy kernel ============================
// CTA: 64 t-rows x 128 attn dims; 8 warps (2m x 4n), warp tile 32x32.
// Single-term fp16; A double-buffered, B TRIPLE-buffered -> one barrier per
// chunk with no WAR aliasing (UNCHANGED from R14 — proven correct/fast).
__global__ __launch_bounds__(256, 3)
void energy_kernel(const float* __restrict__ enc,
                   const float* __restrict__ prev,
                   const float* __restrict__ v) {
    extern __shared__ char smraw[];
    const uint32_t raw = smem_u32(smraw);
    const uint32_t base = (raw + 1023u) & ~1023u;
    char* sm = smraw + (base - raw);

    const int b    = blockIdx.y;
    const int t0   = blockIdx.x * MT;
    const int tid  = threadIdx.x;
    const int lane = tid & 31;
    const int wid  = tid >> 5;
    const int warp_m = (wid >> 2) * 32;   // 2 m-tiles of 32
    const int warp_n = (wid & 3) * 32;    // 4 n-tiles of 32

    float* qb_s = (float*)(sm + OFF_QB);
    float* vv_s = (float*)(sm + OFF_VV);
    float* pv_s = (float*)(sm + OFF_PREV);
    float* part = (float*)(sm + OFF_PART);

    if (tid < AD) {
        qb_s[tid] = g_qb[b * AD + tid];
        vv_s[tid] = v[tid];
    }
    if (tid < MT + KS - 1) {
        int tg = t0 + tid - PADK;
        pv_s[tid] = (tg >= 0 && tg < T_) ? prev[b * T_ + tg] : 0.f;
    }
    // first loop sync publishes pv_s/qb/vv (pv_s first read at c=6; qb/vv epi)

    float acc[2][4][4];
    #pragma unroll
    for (int mt = 0; mt < 2; mt++)
        #pragma unroll
        for (int j = 0; j < 4; j++)
            #pragma unroll
            for (int r = 0; r < 4; r++) acc[mt][j][r] = 0.f;

    const float* encb = enc + ((size_t)b * T_ + t0) * ENC;
    float stA[2][8];

    // prologue: A(0) -> smem buf0; B(0),B(1) in flight; A(1) staged in regs
    stage_A_fn(stA, 0, tid, encb, pv_s);
    sts_A_fn(stA, 0, tid, sm);
    fill_B_fn(0, tid, base); CPCOMMIT();
    fill_B_fn(1, tid, base); CPCOMMIT();
    stage_A_fn(stA, 1, tid, encb, pv_s);

    for (int c = 0; c < NCHUNK; c++) {
        if (c < 8) CPWAIT1(); else CPWAIT0();   // B(c) complete
        __syncthreads();   // A(c) STS visible; all MMA(c-1) done
        const uint32_t aa = base + OFF_A + (uint32_t)(c & 1) * ASTAGE;
        const uint32_t bb = base + OFF_B + (uint32_t)(c % 3) * BSTAGE;
        // ---- mma over this chunk: 4 k16 steps; 4 LDSM + 8 MMA per kk ----
        #pragma unroll
        for (int kk = 0; kk < 4; kk++) {
            const uint32_t kb  = (uint32_t)(kk * 32) + ((lane >> 4) & 1) * 16;
            const uint32_t kbb = (uint32_t)(kk * 32) + ((lane >> 3) & 1) * 16;
            uint32_t ah[2][4];
            uint32_t bf[2][4];
            #pragma unroll
            for (int mt = 0; mt < 2; mt++) {
                int row = warp_m + mt * 16 + (lane & 15);
                uint32_t off = sw128((uint32_t)(row * 128) + kb);
                LDSM4(ah[mt][0], ah[mt][1], ah[mt][2], ah[mt][3], aa + off);
            }
            #pragma unroll
            for (int q = 0; q < 2; q++) {
                int n = warp_n + q * 16 + ((lane >> 4) << 3) + (lane & 7);
                uint32_t off = sw128((uint32_t)(n * 128) + kbb);
                LDSM4(bf[q][0], bf[q][1], bf[q][2], bf[q][3], bb + off);
            }
            #pragma unroll
            for (int mt = 0; mt < 2; mt++) {
                #pragma unroll
                for (int q = 0; q < 2; q++) {
                    MMAH(acc[mt][q * 2],     ah[mt], bf[q][0], bf[q][1]);
                    MMAH(acc[mt][q * 2 + 1], ah[mt], bf[q][2], bf[q][3]);
                }
            }
        }
        // ---- post-MMA (unfenced; targets fenced by sync(c) are safe) ----
        if (c < 8) {
            sts_A_fn(stA, (c + 1) & 1, tid, sm);
            if (c < 7) {
                fill_B_fn(c + 2, tid, base); CPCOMMIT();
                stage_A_fn(stA, c + 2, tid, encb, pv_s);
            }
        }
    }

    // ---- epilogue: tanh + dot(v) + reduce ----
    float pr[4] = {0.f, 0.f, 0.f, 0.f};
    #pragma unroll
    for (int mt = 0; mt < 2; mt++) {
        #pragma unroll
        for (int j = 0; j < 4; j++) {
            int n0 = warp_n + j * 8 + 2 * (lane & 3);
            float v0 = vv_s[n0], v1 = vv_s[n0 + 1];
            float q0 = qb_s[n0], q1 = qb_s[n0 + 1];
            #pragma unroll
            for (int rh = 0; rh < 2; rh++) {
                float x0 = acc[mt][j][rh * 2]     + q0;
                float x1 = acc[mt][j][rh * 2 + 1] + q1;
                x0 = fminf(fmaxf(x0, -15.f), 15.f);
                x1 = fminf(fmaxf(x1, -15.f), 15.f);
                float e0 = __expf(2.f * x0), e1 = __expf(2.f * x1);
                float th0 = (e0 - 1.f) * __frcp_rn(e0 + 1.f);
                float th1 = (e1 - 1.f) * __frcp_rn(e1 + 1.f);
                pr[mt * 2 + rh] += th0 * v0 + th1 * v1;
            }
        }
    }
    #pragma unroll
    for (int i = 0; i < 4; i++) {
        pr[i] += __shfl_xor_sync(0xffffffffu, pr[i], 1);
        pr[i] += __shfl_xor_sync(0xffffffffu, pr[i], 2);
    }
    const int wn = wid & 3;
    if ((lane & 3) == 0) {
        int rbase = warp_m + (lane >> 2);
        part[wn * MT + rbase]      = pr[0];
        part[wn * MT + rbase + 8]  = pr[1];
        part[wn * MT + rbase + 16] = pr[2];
        part[wn * MT + rbase + 24] = pr[3];
    }
    __syncthreads();
    if (tid < MT)
        g_energy[b * T_ + t0 + tid] = part[tid] + part[MT + tid]
                                    + part[2 * MT + tid] + part[3 * MT + tid];
}

// ============================ softmax ============================
__global__ __launch_bounds__(512)
void softmax_kernel(float* __restrict__ out) {
    __shared__ float red[16];
    const int b = blockIdx.x, tid = threadIdx.x;
    const int lane = tid & 31, warp = tid >> 5;
    const float4* e4 = (const float4*)(g_energy + b * T_);
    float4 f = e4[tid];

    float mx = fmaxf(fmaxf(f.x, f.y), fmaxf(f.z, f.w));
    #pragma unroll
    for (int o = 16; o; o >>= 1)
        mx = fmaxf(mx, __shfl_xor_sync(0xffffffffu, mx, o));
    if (lane == 0) red[warp] = mx;
    __syncthreads();
    mx = red[lane & 15];
    #pragma unroll
    for (int o = 8; o; o >>= 1)
        mx = fmaxf(mx, __shfl_xor_sync(0xffffffffu, mx, o));

    float4 ex;
    ex.x = __expf(f.x - mx); ex.y = __expf(f.y - mx);
    ex.z = __expf(f.z - mx); ex.w = __expf(f.w - mx);
    float sum = ex.x + ex.y + ex.z + ex.w;
    #pragma unroll
    for (int o = 16; o; o >>= 1)
        sum += __shfl_xor_sync(0xffffffffu, sum, o);
    __syncthreads();
    if (lane == 0) red[warp] = sum;
    __syncthreads();
    sum = red[lane & 15];
    #pragma unroll
    for (int o = 8; o; o >>= 1)
        sum += __shfl_xor_sync(0xffffffffu, sum, o);
    float inv = 1.f / sum;

    float4 o4; o4.x = ex.x*inv; o4.y = ex.y*inv; o4.z = ex.z*inv; o4.w = ex.w*inv;
    ((float4*)(out + b * T_))[tid] = o4;
}

// ============================ launch ============================
extern "C" void kernel_launch(void* const* d_in, const int* in_sizes, int n_in,
                              void* d_out, int out_size) {
    const float* enc    = (const float*)d_in[0];
    const float* dec    = (const float*)d_in[1];
    const float* prev   = (const float*)d_in[2];
    const float* Wq     = (const float*)d_in[3];
    const float* Wk     = (const float*)d_in[4];
    const float* conv_w = (const float*)d_in[5];
    const float* conv_b = (const float*)d_in[6];
    const float* Wl     = (const float*)d_in[7];
    const float* v      = (const float*)d_in[8];
    float* out = (float*)d_out;

    cudaFuncSetAttribute(energy_kernel,
                         cudaFuncAttributeMaxDynamicSharedMemorySize, SMEM_REQ);

    prep_all_kernel<<<160, 512>>>(Wk, conv_w, Wl, dec, Wq, conv_b);
    energy_kernel<<<dim3(T_ / MT, B_), 256, SMEM_REQ>>>(enc, prev, v);
    softmax_kernel<<<B_, 512>>>(out);
}